// round 3
// baseline (speedup 1.0000x reference)
#include <cuda_runtime.h>
#include <cstdint>

typedef unsigned long long u64;
typedef unsigned int u32;

#define Nn 8
#define Cc 80
#define HWp 25600
#define PER_IMG (Cc*HWp)        // 2048000
#define F4_PER_IMG (PER_IMG/4)  // 512000
#define BINS 8192
#define CAP 4096
#define KP 1024
#define KK 1000
#define POST 100

// ---------------- scratch (device globals; no allocs allowed) ----------------
__device__ float g_ctrs[Nn*HWp];
__device__ u32   g_hist[Nn*BINS];
__device__ u32   g_tbits[Nn];
__device__ int   g_cnt[Nn];
__device__ u64   g_cand[Nn*CAP];
__device__ float g_score[Nn*KP];
__device__ float g_boxes[Nn*KP*4];
__device__ int   g_label[Nn*KP];
__device__ int   g_validf[Nn*KP];
__device__ float g_maxo[Nn];
__device__ u64   g_mask[Nn*KP*16];
__device__ u64   g_keep64[Nn*16];

// ---------------- helpers ----------------
__device__ __forceinline__ float sigmoidf_(float x) {
    return 1.0f / (1.0f + expf(-x));
}

// ---------------- kernels ----------------
__global__ void k_reset() {
    int i = blockIdx.x*blockDim.x + threadIdx.x;
    int stride = gridDim.x*blockDim.x;
    for (int t = i; t < Nn*BINS; t += stride) g_hist[t] = 0u;
    for (int t = i; t < Nn*CAP; t += stride) g_cand[t] = ~0ULL;
    if (i < Nn) g_cnt[i] = 0;
}

__global__ void k_ctr(const float* __restrict__ ctr) {
    int i = blockIdx.x*blockDim.x + threadIdx.x;
    if (i < Nn*HWp) g_ctrs[i] = sigmoidf_(ctr[i]);
}

// pass 1: per-image histogram of score float-bits >> 17
__global__ void k_hist(const float* __restrict__ cls) {
    __shared__ u32 sh[BINS];
    for (int b = threadIdx.x; b < BINS; b += blockDim.x) sh[b] = 0u;
    __syncthreads();
    int n = blockIdx.y;
    const float4* cls4 = (const float4*)(cls + (size_t)n*PER_IMG);
    const float4* cs4  = (const float4*)(g_ctrs + n*HWp);
    int t4 = blockIdx.x*2048 + threadIdx.x;
    #pragma unroll
    for (int it = 0; it < 8; it++, t4 += 256) {
        int e = t4*4;
        int c = e / HWp;
        int pix = e - c*HWp;
        float4 x = cls4[t4];
        float4 cv = cs4[pix >> 2];
        {
            float p = sigmoidf_(x.x);
            if (p > 0.05f) { float s = p*cv.x; atomicAdd(&sh[__float_as_uint(s)>>17], 1u); }
        }
        {
            float p = sigmoidf_(x.y);
            if (p > 0.05f) { float s = p*cv.y; atomicAdd(&sh[__float_as_uint(s)>>17], 1u); }
        }
        {
            float p = sigmoidf_(x.z);
            if (p > 0.05f) { float s = p*cv.z; atomicAdd(&sh[__float_as_uint(s)>>17], 1u); }
        }
        {
            float p = sigmoidf_(x.w);
            if (p > 0.05f) { float s = p*cv.w; atomicAdd(&sh[__float_as_uint(s)>>17], 1u); }
        }
    }
    __syncthreads();
    for (int b = threadIdx.x; b < BINS; b += blockDim.x) {
        u32 v = sh[b];
        if (v) atomicAdd(&g_hist[n*BINS + b], v);
    }
}

// find smallest bin B with suffix count >= 1000; threshold bits = B<<17
__global__ void k_thresh() {
    int n = blockIdx.x;
    __shared__ u32 segs[256];
    const u32* h = g_hist + n*BINS;
    u32 s = 0;
    int base = threadIdx.x*32;
    for (int b = 0; b < 32; b++) s += h[base + b];
    segs[threadIdx.x] = s;
    __syncthreads();
    if (threadIdx.x == 0) {
        u32 cum = 0;
        int B = 0;
        bool found = false;
        for (int t = 255; t >= 0 && !found; t--) {
            if (cum + segs[t] >= (u32)KK) {
                for (int b = t*32 + 31; b >= t*32; b--) {
                    cum += h[b];
                    if (cum >= (u32)KK) { B = b; found = true; break; }
                }
            } else {
                cum += segs[t];
            }
        }
        g_tbits[n] = ((u32)B) << 17;
    }
}

// pass 2: compact candidates above threshold: key = (~score_bits<<32)|flat_idx
__global__ void k_collect(const float* __restrict__ cls) {
    int n = blockIdx.y;
    u32 tb = g_tbits[n];
    const float4* cls4 = (const float4*)(cls + (size_t)n*PER_IMG);
    const float4* cs4  = (const float4*)(g_ctrs + n*HWp);
    int t4 = blockIdx.x*2048 + threadIdx.x;
    #pragma unroll
    for (int it = 0; it < 8; it++, t4 += 256) {
        int e = t4*4;
        int c = e / HWp;
        int pix = e - c*HWp;
        float4 x = cls4[t4];
        float4 cv = cs4[pix >> 2];
        float pv[4] = {x.x, x.y, x.z, x.w};
        float cc[4] = {cv.x, cv.y, cv.z, cv.w};
        #pragma unroll
        for (int k = 0; k < 4; k++) {
            float p = sigmoidf_(pv[k]);
            if (p > 0.05f) {
                float s = p*cc[k];
                u32 sb = __float_as_uint(s);
                if (sb >= tb) {
                    int pos = atomicAdd(&g_cnt[n], 1);
                    if (pos < CAP) {
                        u32 idx = (u32)(pix + k)*80u + (u32)c;
                        g_cand[n*CAP + pos] = (((u64)(~sb)) << 32) | (u64)idx;
                    }
                }
            }
        }
    }
}

// bitonic sort 4096 keys ascending (= score desc, idx asc), then decode boxes + max_c
__global__ void k_sortdecode(const float* __restrict__ reg,
                             const float* __restrict__ pts,
                             const float* __restrict__ imsz) {
    __shared__ u64 sk[CAP];
    __shared__ float red[512];
    int n = blockIdx.x, tid = threadIdx.x;
    for (int i = tid; i < CAP; i += 512) sk[i] = g_cand[n*CAP + i];
    __syncthreads();
    for (int k2 = 2; k2 <= CAP; k2 <<= 1) {
        for (int j = k2 >> 1; j > 0; j >>= 1) {
            for (int i = tid; i < CAP; i += 512) {
                int p = i ^ j;
                if (p > i) {
                    u64 a = sk[i], b = sk[p];
                    bool up = ((i & k2) == 0);
                    if ((a > b) == up) { sk[i] = b; sk[p] = a; }
                }
            }
            __syncthreads();
        }
    }
    float w1 = imsz[n*2] - 1.0f;
    float h1 = imsz[n*2 + 1] - 1.0f;
    const float* rg = reg + (size_t)n*4*HWp;
    float mx = 0.0f;
    for (int r = tid; r < KP; r += 512) {
        u64 key = sk[r];
        float val; int valid; u32 idx;
        if (key == ~0ULL || r >= KK) { val = -1.0f; valid = 0; idx = 0; }
        else {
            u32 sb = ~((u32)(key >> 32));
            val = __uint_as_float(sb);
            idx = (u32)key;
            valid = (val >= 0.0f) ? 1 : 0;
        }
        u32 c = idx % 80u;
        u32 loc = idx / 80u;
        float px = pts[loc*2], py = pts[loc*2 + 1];
        float d0 = rg[loc], d1 = rg[HWp + loc], d2 = rg[2*HWp + loc], d3 = rg[3*HWp + loc];
        float x1 = fminf(fmaxf(px - d0, 0.0f), w1);
        float y1 = fminf(fmaxf(py - d1, 0.0f), h1);
        float x2 = fminf(fmaxf(px + d2, 0.0f), w1);
        float y2 = fminf(fmaxf(py + d3, 0.0f), h1);
        int o = (n*KP + r)*4;
        g_boxes[o] = x1; g_boxes[o+1] = y1; g_boxes[o+2] = x2; g_boxes[o+3] = y2;
        g_label[n*KP + r] = (int)c + 1;
        g_validf[n*KP + r] = valid;
        g_score[n*KP + r] = valid ? sqrtf(fmaxf(val, 0.0f)) : -1.0f;
        if (valid) mx = fmaxf(mx, fmaxf(fmaxf(x1, x2), fmaxf(y1, y2)));
    }
    red[tid] = mx;
    __syncthreads();
    for (int s = 256; s > 0; s >>= 1) {
        if (tid < s) red[tid] = fmaxf(red[tid], red[tid + s]);
        __syncthreads();
    }
    if (tid == 0) g_maxo[n] = red[0] + 1.0f;
}

// 64x64 IoU tiles -> suppression bitmask (only j>i)
__global__ void k_mask() {
    int n = blockIdx.z, ti = blockIdx.y, tj = blockIdx.x;
    if (tj < ti) return;
    int t = threadIdx.x;
    float maxo = g_maxo[n];
    int i = ti*64 + t;
    int oi = (n*KP + i)*4;
    float offi = (float)g_label[n*KP + i] * maxo;
    float ax1 = g_boxes[oi]   + offi;
    float ay1 = g_boxes[oi+1] + offi;
    float ax2 = g_boxes[oi+2] + offi;
    float ay2 = g_boxes[oi+3] + offi;
    float areai = (ax2 - ax1)*(ay2 - ay1);
    __shared__ float sb[64][5];
    int j0 = tj*64 + t;
    int oj = (n*KP + j0)*4;
    float offj = (float)g_label[n*KP + j0] * maxo;
    sb[t][0] = g_boxes[oj]   + offj;
    sb[t][1] = g_boxes[oj+1] + offj;
    sb[t][2] = g_boxes[oj+2] + offj;
    sb[t][3] = g_boxes[oj+3] + offj;
    sb[t][4] = (sb[t][2] - sb[t][0])*(sb[t][3] - sb[t][1]);
    __syncthreads();
    u64 bits = 0;
    if (i < KK) {
        int jbase = tj*64;
        #pragma unroll 4
        for (int jj = 0; jj < 64; jj++) {
            int j = jbase + jj;
            if (j <= i || j >= KK) continue;
            float xx1 = fmaxf(ax1, sb[jj][0]);
            float yy1 = fmaxf(ay1, sb[jj][1]);
            float xx2 = fminf(ax2, sb[jj][2]);
            float yy2 = fminf(ay2, sb[jj][3]);
            float inter = fmaxf(xx2 - xx1, 0.0f)*fmaxf(yy2 - yy1, 0.0f);
            float den = fmaxf(areai + sb[jj][4] - inter, 1e-6f);
            float iou = inter / den;
            if (iou > 0.6f) bits |= 1ull << jj;
        }
    }
    g_mask[(size_t)(n*KP + i)*16 + tj] = bits;
}

// chunked serial NMS scan: 64-entry diagonal blocks resolved by one thread,
// cross-chunk ORs done in parallel.
__global__ void __launch_bounds__(128) k_scan() {
    int n = blockIdx.x, t = threadIdx.x;
    __shared__ u64 rem[16];
    __shared__ u64 diag[64];
    __shared__ u64 keepw[16];
    if (t < 16) {
        u64 b = 0;
        for (int k = 0; k < 64; k++)
            if (!g_validf[n*KP + t*64 + k]) b |= 1ull << k;
        rem[t] = b;
    }
    __syncthreads();
    for (int c = 0; c < 16; c++) {
        if (t < 64) diag[t] = g_mask[(size_t)(n*KP + c*64 + t)*16 + c];
        __syncthreads();
        if (t == 0) {
            u64 mm[64];
            #pragma unroll
            for (int b = 0; b < 64; b++) mm[b] = diag[b];
            u64 rcur = rem[c], kb = 0;
            #pragma unroll
            for (int b = 0; b < 64; b++) {
                u64 alive = ((rcur >> b) & 1ull) ^ 1ull;
                kb |= alive << b;
                rcur |= alive ? mm[b] : 0ull;
            }
            rem[c] = rcur;
            keepw[c] = kb;
        }
        __syncthreads();
        u64 kb = keepw[c];
        for (int q = t; q < 1024; q += 128) {
            int b = q & 63, w = q >> 6;
            if (w > c && ((kb >> b) & 1ull)) {
                u64 v = g_mask[(size_t)(n*KP + c*64 + b)*16 + w];
                if (v) atomicOr(&rem[w], v);
            }
        }
        __syncthreads();
    }
    if (t < 16) g_keep64[n*16 + t] = keepw[t];
}

// final top-100 per image: kept entries in score order, then lowest-index non-kept
__global__ void k_out(float* __restrict__ out, int out_size) {
    int n = blockIdx.x, t = threadIdx.x;
    __shared__ int list[POST];
    __shared__ int mk;
    if (t == 0) {
        int m = 0;
        for (int i = 0; i < KK && m < POST; i++) {
            if ((g_keep64[n*16 + (i >> 6)] >> (i & 63)) & 1ull) list[m++] = i;
        }
        mk = m;
        for (int i = 0; i < KK && m < POST; i++) {
            if (!((g_keep64[n*16 + (i >> 6)] >> (i & 63)) & 1ull)) list[m++] = i;
        }
    }
    __syncthreads();
    if (t < POST) {
        int j = list[t];
        bool ov = t < mk;
        int ob = (n*KP + j)*4;
        int base = n*POST*5 + t*5;
        if (base + 4 < out_size) {
            out[base]     = g_boxes[ob];
            out[base + 1] = g_boxes[ob + 1];
            out[base + 2] = g_boxes[ob + 2];
            out[base + 3] = g_boxes[ob + 3];
            out[base + 4] = ov ? g_score[n*KP + j] : 0.0f;
        }
        int lb = Nn*POST*5 + n*POST + t;
        if (lb < out_size) out[lb] = ov ? (float)g_label[n*KP + j] : 0.0f;
        int vb = Nn*POST*5 + Nn*POST + n*POST + t;
        if (vb < out_size) out[vb] = ov ? 1.0f : 0.0f;
    }
}

extern "C" void kernel_launch(void* const* d_in, const int* in_sizes, int n_in,
                              void* d_out, int out_size) {
    const float* cls  = (const float*)d_in[0];
    const float* reg  = (const float*)d_in[1];
    const float* ctr  = (const float*)d_in[2];
    const float* pts  = (const float*)d_in[3];
    const float* imsz = (const float*)d_in[4];

    k_reset<<<256, 256>>>();
    k_ctr<<<(Nn*HWp + 255)/256, 256>>>(ctr);
    k_hist<<<dim3(250, 8), 256>>>(cls);
    k_thresh<<<8, 256>>>();
    k_collect<<<dim3(250, 8), 256>>>(cls);
    k_sortdecode<<<8, 512>>>(reg, pts, imsz);
    k_mask<<<dim3(16, 16, 8), 64>>>();
    k_scan<<<8, 128>>>();
    k_out<<<8, 128>>>((float*)d_out, out_size);
}

// round 4
// speedup vs baseline: 1.3884x; 1.3884x over previous
#include <cuda_runtime.h>
#include <cstdint>

typedef unsigned long long u64;
typedef unsigned int u32;

#define Nn 8
#define Cc 80
#define HWp 25600
#define PER_IMG (Cc*HWp)        // 2048000
#define BINS 8192
#define CAP 4096
#define CAP_SPEC 65536
#define STAGE 512
#define KP 1024
#define KK 1000
#define POST 100
#define SPEC_BITS 0x3F333333u   /* bits of 0.70f */

// ---------------- scratch (device globals; no allocs allowed) ----------------
__device__ float g_ctrs[Nn*HWp];
__device__ u32   g_hist[Nn*BINS];
__device__ u32   g_tbits[Nn];
__device__ int   g_scnt[Nn];
__device__ int   g_fb[Nn];
__device__ int   g_cnt[Nn];
__device__ u64   g_spec[Nn*CAP_SPEC];
__device__ u64   g_cand[Nn*CAP];
__device__ float g_score[Nn*KP];
__device__ float g_boxes[Nn*KP*4];
__device__ int   g_label[Nn*KP];
__device__ int   g_validf[Nn*KP];
__device__ float g_maxo[Nn];
__device__ u64   g_mask[Nn*KP*16];

__device__ __forceinline__ float sigmoidf_(float x) {
    return 1.0f / (1.0f + expf(-x));
}

// ---------------- fused reset + centerness sigmoid ----------------
__global__ void k_prep(const float* __restrict__ ctr) {
    int i = blockIdx.x*blockDim.x + threadIdx.x;
    if (i < Nn*HWp) g_ctrs[i] = sigmoidf_(ctr[i]);
    if (i < Nn*BINS) g_hist[i] = 0u;
    if (i < Nn*CAP) g_cand[i] = ~0ULL;
    if (i < Nn) { g_cnt[i] = 0; g_scnt[i] = 0; g_fb[i] = 0; }
}

// ---------------- pass 1: histogram + speculative collect (score >= 0.70) ----------------
__global__ void k_hist(const float* __restrict__ cls) {
    __shared__ u32 sh[BINS];
    __shared__ u64 stage[STAGE];
    __shared__ int scnt_s;
    __shared__ int base_s;
    for (int b = threadIdx.x; b < BINS; b += blockDim.x) sh[b] = 0u;
    if (threadIdx.x == 0) scnt_s = 0;
    __syncthreads();
    int n = blockIdx.y;
    const float4* cls4 = (const float4*)(cls + (size_t)n*PER_IMG);
    const float4* cs4  = (const float4*)(g_ctrs + n*HWp);
    int t4 = blockIdx.x*2048 + threadIdx.x;
    #pragma unroll
    for (int it = 0; it < 8; it++, t4 += 256) {
        int e = t4*4;
        int c = e / HWp;
        int pix = e - c*HWp;
        float4 x = cls4[t4];
        float4 cv = cs4[pix >> 2];
        float pv[4] = {x.x, x.y, x.z, x.w};
        float cc[4] = {cv.x, cv.y, cv.z, cv.w};
        #pragma unroll
        for (int k = 0; k < 4; k++) {
            float p = sigmoidf_(pv[k]);
            if (p > 0.05f) {
                float s = p*cc[k];
                u32 sb = __float_as_uint(s);
                atomicAdd(&sh[sb >> 17], 1u);
                if (sb >= SPEC_BITS) {
                    u32 idx = (u32)(pix + k)*80u + (u32)c;
                    u64 key = (((u64)(~sb)) << 32) | (u64)idx;
                    int pos = atomicAdd(&scnt_s, 1);
                    if (pos < STAGE) stage[pos] = key;
                    else {
                        int gp = atomicAdd(&g_scnt[n], 1);
                        if (gp < CAP_SPEC) g_spec[n*CAP_SPEC + gp] = key;
                    }
                }
            }
        }
    }
    __syncthreads();
    for (int b = threadIdx.x; b < BINS; b += blockDim.x) {
        u32 v = sh[b];
        if (v) atomicAdd(&g_hist[n*BINS + b], v);
    }
    int m = scnt_s < STAGE ? scnt_s : STAGE;
    if (threadIdx.x == 0 && m > 0) base_s = atomicAdd(&g_scnt[n], m);
    __syncthreads();
    for (int i = threadIdx.x; i < m; i += blockDim.x) {
        int gp = base_s + i;
        if (gp < CAP_SPEC) g_spec[n*CAP_SPEC + gp] = stage[i];
    }
}

// ---------------- parallel threshold: suffix scan over 8192 bins ----------------
__global__ void k_thresh() {
    int n = blockIdx.x, t = threadIdx.x;
    __shared__ u32 suf[256];
    const u32* h = g_hist + n*BINS;
    const uint4* h4 = ((const uint4*)h) + t*8;
    u32 s = 0;
    #pragma unroll
    for (int q = 0; q < 8; q++) { uint4 v = h4[q]; s += v.x + v.y + v.z + v.w; }
    suf[t] = s;
    __syncthreads();
    for (int off = 1; off < 256; off <<= 1) {
        u32 add = (t + off < 256) ? suf[t + off] : 0u;
        __syncthreads();
        suf[t] += add;
        __syncthreads();
    }
    u32 mine = suf[t];
    u32 nxt = (t < 255) ? suf[t + 1] : 0u;
    if (mine >= (u32)KK && nxt < (u32)KK) {
        u32 cum = nxt;
        int B = t*32;
        for (int b = t*32 + 31; b >= t*32; b--) {
            cum += h[b];
            if (cum >= (u32)KK) { B = b; break; }
        }
        u32 tb = ((u32)B) << 17;
        g_tbits[n] = tb;
        g_fb[n] = (tb < SPEC_BITS || g_scnt[n] > CAP_SPEC) ? 1 : 0;
    }
    if (t == 0 && suf[0] < (u32)KK) { g_tbits[n] = 0u; g_fb[n] = 1; }
}

// ---------------- filter spec buffer (common) or full recompute (fallback) ----------------
__global__ void k_filter(const float* __restrict__ cls) {
    int n = blockIdx.y;
    u32 tb = g_tbits[n];
    if (!g_fb[n]) {
        int m = g_scnt[n]; if (m > CAP_SPEC) m = CAP_SPEC;
        for (int i = blockIdx.x*blockDim.x + threadIdx.x; i < m; i += gridDim.x*blockDim.x) {
            u64 key = g_spec[n*CAP_SPEC + i];
            u32 sb = ~((u32)(key >> 32));
            if (sb >= tb) {
                int pos = atomicAdd(&g_cnt[n], 1);
                if (pos < CAP) g_cand[n*CAP + pos] = key;
            }
        }
    } else {
        const float4* cls4 = (const float4*)(cls + (size_t)n*PER_IMG);
        const float4* cs4  = (const float4*)(g_ctrs + n*HWp);
        int t4 = blockIdx.x*2048 + threadIdx.x;
        #pragma unroll
        for (int it = 0; it < 8; it++, t4 += 256) {
            int e = t4*4;
            int c = e / HWp;
            int pix = e - c*HWp;
            float4 x = cls4[t4];
            float4 cv = cs4[pix >> 2];
            float pv[4] = {x.x, x.y, x.z, x.w};
            float cc[4] = {cv.x, cv.y, cv.z, cv.w};
            #pragma unroll
            for (int k = 0; k < 4; k++) {
                float p = sigmoidf_(pv[k]);
                if (p > 0.05f) {
                    float s = p*cc[k];
                    u32 sb = __float_as_uint(s);
                    if (sb >= tb) {
                        int pos = atomicAdd(&g_cnt[n], 1);
                        if (pos < CAP) {
                            u32 idx = (u32)(pix + k)*80u + (u32)c;
                            g_cand[n*CAP + pos] = (((u64)(~sb)) << 32) | (u64)idx;
                        }
                    }
                }
            }
        }
    }
}

// ---------------- bitonic sort (2048 or 4096) + box decode + max_c ----------------
__global__ void k_sortdecode(const float* __restrict__ reg,
                             const float* __restrict__ pts,
                             const float* __restrict__ imsz) {
    __shared__ u64 sk[CAP];
    __shared__ float red[1024];
    int n = blockIdx.x, tid = threadIdx.x;
    int cnt = g_cnt[n]; if (cnt > CAP) cnt = CAP;
    int S = (cnt <= 2048) ? 2048 : 4096;
    for (int i = tid; i < S; i += 1024) sk[i] = g_cand[n*CAP + i];
    __syncthreads();
    for (int k2 = 2; k2 <= S; k2 <<= 1) {
        for (int j = k2 >> 1; j > 0; j >>= 1) {
            for (int i = tid; i < S; i += 1024) {
                int p = i ^ j;
                if (p > i) {
                    u64 a = sk[i], b = sk[p];
                    bool up = ((i & k2) == 0);
                    if ((a > b) == up) { sk[i] = b; sk[p] = a; }
                }
            }
            __syncthreads();
        }
    }
    float w1 = imsz[n*2] - 1.0f;
    float h1 = imsz[n*2 + 1] - 1.0f;
    const float* rg = reg + (size_t)n*4*HWp;
    float mx = 0.0f;
    {
        int r = tid;                       // KP == blockDim == 1024
        u64 key = sk[r];
        float val; int valid; u32 idx;
        if (key == ~0ULL || r >= KK) { val = -1.0f; valid = 0; idx = 0; }
        else {
            u32 sb = ~((u32)(key >> 32));
            val = __uint_as_float(sb);
            idx = (u32)key;
            valid = (val >= 0.0f) ? 1 : 0;
        }
        u32 c = idx % 80u;
        u32 loc = idx / 80u;
        float px = pts[loc*2], py = pts[loc*2 + 1];
        float d0 = rg[loc], d1 = rg[HWp + loc], d2 = rg[2*HWp + loc], d3 = rg[3*HWp + loc];
        float x1 = fminf(fmaxf(px - d0, 0.0f), w1);
        float y1 = fminf(fmaxf(py - d1, 0.0f), h1);
        float x2 = fminf(fmaxf(px + d2, 0.0f), w1);
        float y2 = fminf(fmaxf(py + d3, 0.0f), h1);
        int o = (n*KP + r)*4;
        g_boxes[o] = x1; g_boxes[o+1] = y1; g_boxes[o+2] = x2; g_boxes[o+3] = y2;
        g_label[n*KP + r] = (int)c + 1;
        g_validf[n*KP + r] = valid;
        g_score[n*KP + r] = valid ? sqrtf(fmaxf(val, 0.0f)) : -1.0f;
        mx = valid ? fmaxf(fmaxf(x1, x2), fmaxf(y1, y2)) : 0.0f;
    }
    red[tid] = mx;
    __syncthreads();
    for (int s = 512; s > 0; s >>= 1) {
        if (tid < s) red[tid] = fmaxf(red[tid], red[tid + s]);
        __syncthreads();
    }
    if (tid == 0) g_maxo[n] = red[0] + 1.0f;
}

// ---------------- 64x64 IoU tiles -> suppression bitmask (j>i only) ----------------
__global__ void k_mask() {
    int n = blockIdx.z, ti = blockIdx.y, tj = blockIdx.x;
    if (tj < ti) return;
    int t = threadIdx.x;
    float maxo = g_maxo[n];
    int i = ti*64 + t;
    int oi = (n*KP + i)*4;
    float offi = (float)g_label[n*KP + i] * maxo;
    float ax1 = g_boxes[oi]   + offi;
    float ay1 = g_boxes[oi+1] + offi;
    float ax2 = g_boxes[oi+2] + offi;
    float ay2 = g_boxes[oi+3] + offi;
    float areai = (ax2 - ax1)*(ay2 - ay1);
    __shared__ float sb[64][5];
    int j0 = tj*64 + t;
    int oj = (n*KP + j0)*4;
    float offj = (float)g_label[n*KP + j0] * maxo;
    sb[t][0] = g_boxes[oj]   + offj;
    sb[t][1] = g_boxes[oj+1] + offj;
    sb[t][2] = g_boxes[oj+2] + offj;
    sb[t][3] = g_boxes[oj+3] + offj;
    sb[t][4] = (sb[t][2] - sb[t][0])*(sb[t][3] - sb[t][1]);
    __syncthreads();
    u64 bits = 0;
    if (i < KK) {
        int jbase = tj*64;
        #pragma unroll 4
        for (int jj = 0; jj < 64; jj++) {
            int j = jbase + jj;
            if (j <= i || j >= KK) continue;
            float xx1 = fmaxf(ax1, sb[jj][0]);
            float yy1 = fmaxf(ay1, sb[jj][1]);
            float xx2 = fminf(ax2, sb[jj][2]);
            float yy2 = fminf(ay2, sb[jj][3]);
            float inter = fmaxf(xx2 - xx1, 0.0f)*fmaxf(yy2 - yy1, 0.0f);
            float den = fmaxf(areai + sb[jj][4] - inter, 1e-6f);
            if (inter / den > 0.6f) bits |= 1ull << jj;
        }
    }
    g_mask[(size_t)(n*KP + i)*16 + tj] = bits;
}

// ---------------- fused NMS scan + top-100 output ----------------
__global__ void __launch_bounds__(128, 1) k_scanout(float* __restrict__ out, int out_size) {
    int n = blockIdx.x, t = threadIdx.x;
    __shared__ u64 rem[16];
    __shared__ u64 diag[64];
    __shared__ u64 keepw[16];
    if (t < 16) {
        u64 b = 0;
        for (int k = 0; k < 64; k++)
            if (!g_validf[n*KP + t*64 + k]) b |= 1ull << k;
        rem[t] = b;
    }
    __syncthreads();
    for (int c = 0; c < 16; c++) {
        if (t < 64) diag[t] = g_mask[(size_t)(n*KP + c*64 + t)*16 + c];
        __syncthreads();
        if (t == 0) {
            u64 mm[64];
            #pragma unroll
            for (int b = 0; b < 64; b++) mm[b] = diag[b];
            u64 rcur = rem[c], kb = 0;
            #pragma unroll
            for (int b = 0; b < 64; b++) {
                u64 alive = ((rcur >> b) & 1ull) ^ 1ull;
                kb |= alive << b;
                rcur |= alive ? mm[b] : 0ull;
            }
            rem[c] = rcur;
            keepw[c] = kb;
        }
        __syncthreads();
        u64 kb = keepw[c];
        for (int q = t; q < 1024; q += 128) {
            int b = q & 63, w = q >> 6;
            if (w > c && ((kb >> b) & 1ull)) {
                u64 v = g_mask[(size_t)(n*KP + c*64 + b)*16 + w];
                if (v) atomicOr(&rem[w], v);
            }
        }
        __syncthreads();
    }
    // parallel top-100 list build: kept (in order), then lowest-index non-kept
    __shared__ int offs[16], noffs[16];
    __shared__ int cnts[16], ncnts[16];
    __shared__ int list[POST];
    __shared__ int mks;
    if (t < 16) {
        u64 vmask = (t == 15) ? ((1ull << 40) - 1ull) : ~0ull;  // bits i < 1000
        cnts[t]  = __popcll(keepw[t]);
        ncnts[t] = __popcll(~keepw[t] & vmask);
    }
    __syncthreads();
    if (t == 0) {
        int acc = 0;
        for (int w = 0; w < 16; w++) { offs[w] = acc; acc += cnts[w]; }
        mks = acc > POST ? POST : acc;
        int acc2 = 0;
        for (int w = 0; w < 16; w++) { noffs[w] = acc2; acc2 += ncnts[w]; }
    }
    __syncthreads();
    if (t < 16) {
        u64 w = keepw[t];
        int off = offs[t];
        while (w && off < POST) { int b = __ffsll(w) - 1; list[off++] = t*64 + b; w &= w - 1; }
        u64 vmask = (t == 15) ? ((1ull << 40) - 1ull) : ~0ull;
        u64 nw = ~keepw[t] & vmask;
        int noff = mks + noffs[t];
        while (nw && noff < POST) { int b = __ffsll(nw) - 1; list[noff++] = t*64 + b; nw &= nw - 1; }
    }
    __syncthreads();
    if (t < POST) {
        int j = list[t];
        bool ov = t < mks;
        int ob = (n*KP + j)*4;
        int base = n*POST*5 + t*5;
        if (base + 4 < out_size) {
            out[base]     = g_boxes[ob];
            out[base + 1] = g_boxes[ob + 1];
            out[base + 2] = g_boxes[ob + 2];
            out[base + 3] = g_boxes[ob + 3];
            out[base + 4] = ov ? g_score[n*KP + j] : 0.0f;
        }
        int lb = Nn*POST*5 + n*POST + t;
        if (lb < out_size) out[lb] = ov ? (float)g_label[n*KP + j] : 0.0f;
        int vb = Nn*POST*5 + Nn*POST + n*POST + t;
        if (vb < out_size) out[vb] = ov ? 1.0f : 0.0f;
    }
}

extern "C" void kernel_launch(void* const* d_in, const int* in_sizes, int n_in,
                              void* d_out, int out_size) {
    const float* cls  = (const float*)d_in[0];
    const float* reg  = (const float*)d_in[1];
    const float* ctr  = (const float*)d_in[2];
    const float* pts  = (const float*)d_in[3];
    const float* imsz = (const float*)d_in[4];

    k_prep<<<800, 256>>>(ctr);
    k_hist<<<dim3(250, 8), 256>>>(cls);
    k_thresh<<<8, 256>>>();
    k_filter<<<dim3(250, 8), 256>>>(cls);
    k_sortdecode<<<8, 1024>>>(reg, pts, imsz);
    k_mask<<<dim3(16, 16, 8), 64>>>();
    k_scanout<<<8, 128>>>((float*)d_out, out_size);
}

// round 5
// speedup vs baseline: 1.4339x; 1.0328x over previous
#include <cuda_runtime.h>
#include <cstdint>

typedef unsigned long long u64;
typedef unsigned int u32;

#define Nn 8
#define Cc 80
#define HWp 25600
#define PER_IMG (Cc*HWp)        // 2048000
#define FINE 64
#define FINE_BASE 8089          // (SPEC_BITS >> 17)
#define CAP 4096
#define CAP_SPEC 65536
#define KP 1024
#define KK 1000
#define POST 100
#define SPEC_BITS 0x3F333333u   /* bits of 0.70f */
#define REJECT_X 0.8400f        /* conservative: sigmoid(0.84)=0.6985 < 0.70 */
#define CSTAGE 4096
#define SSTAGE 512

// ---------------- scratch (device globals; zero-init; counters re-zeroed by k_scanout) ----
__device__ u32   g_fine[Nn*FINE];
__device__ int   g_scnt[Nn];
__device__ int   g_fbforce[Nn];
__device__ u64   g_spec[Nn*CAP_SPEC];
__device__ u32   g_tbits[Nn];
__device__ int   g_fb[Nn];
__device__ float g_score[Nn*KP];
__device__ float g_boxes[Nn*KP*4];
__device__ int   g_label[Nn*KP];
__device__ int   g_validf[Nn*KP];
__device__ float g_maxo[Nn];
__device__ u64   g_mask[Nn*KP*16];

__device__ __forceinline__ float sigmoidf_(float x) {
    return 1.0f / (1.0f + expf(-x));
}

// ---------------- pass 1: stream cls, compact x>=REJECT_X, dense sigmoid, fine hist + spec ----
__global__ void __launch_bounds__(256) k_hist(const float* __restrict__ cls,
                                              const float* __restrict__ ctr) {
    __shared__ float sx[CSTAGE];
    __shared__ u32   se[CSTAGE];
    __shared__ u64   stage[SSTAGE];
    __shared__ u32   fine[FINE];
    __shared__ int cstage_n, sstage_n, sbase;
    if (threadIdx.x < FINE) fine[threadIdx.x] = 0;
    if (threadIdx.x == 0) { cstage_n = 0; sstage_n = 0; }
    __syncthreads();
    int n = blockIdx.y;
    const float4* cls4 = (const float4*)(cls + (size_t)n*PER_IMG);
    int t4 = blockIdx.x*2048 + threadIdx.x;
    // Phase A: stream + compact
    #pragma unroll
    for (int it = 0; it < 8; it++, t4 += 256) {
        float4 x = cls4[t4];
        int e = t4*4;
        float pv[4] = {x.x, x.y, x.z, x.w};
        #pragma unroll
        for (int k = 0; k < 4; k++) {
            if (pv[k] >= REJECT_X) {
                int pos = atomicAdd(&cstage_n, 1);
                if (pos < CSTAGE) { sx[pos] = pv[k]; se[pos] = (u32)(e + k); }
            }
        }
    }
    __syncthreads();
    int m = cstage_n; if (m > CSTAGE) m = CSTAGE;
    // Phase B: dense sigmoid on compacted list
    const float* ctrn = ctr + n*HWp;
    for (int i = threadIdx.x; i < m; i += 256) {
        float xv = sx[i];
        u32 e = se[i];
        u32 c = e / (u32)HWp;
        u32 pix = e - c*(u32)HWp;
        float p = sigmoidf_(xv);
        float cv = sigmoidf_(ctrn[pix]);
        float s = p*cv;
        u32 sb = __float_as_uint(s);
        if (p > 0.05f && sb >= SPEC_BITS) {
            atomicAdd(&fine[(sb >> 17) - FINE_BASE], 1u);
            u64 key = (((u64)(~sb)) << 32) | (u64)(pix*80u + c);
            int pos = atomicAdd(&sstage_n, 1);
            if (pos < SSTAGE) stage[pos] = key;
            else {
                int gp = atomicAdd(&g_scnt[n], 1);
                if (gp < CAP_SPEC) g_spec[n*CAP_SPEC + gp] = key;
            }
        }
    }
    __syncthreads();
    if (threadIdx.x < FINE) {
        u32 v = fine[threadIdx.x];
        if (v) atomicAdd(&g_fine[n*FINE + threadIdx.x], v);
    }
    int sm = sstage_n < SSTAGE ? sstage_n : SSTAGE;
    if (threadIdx.x == 0 && sm > 0) sbase = atomicAdd(&g_scnt[n], sm);
    __syncthreads();
    for (int i = threadIdx.x; i < sm; i += 256) {
        int gp = sbase + i;
        if (gp < CAP_SPEC) g_spec[n*CAP_SPEC + gp] = stage[i];
    }
    if (threadIdx.x == 0 && cstage_n > CSTAGE) g_fbforce[n] = 1;
}

// ---------------- threshold from fine hist; full-histogram parachute if guards trip ------
__global__ void __launch_bounds__(1024) k_fbthresh(const float* __restrict__ cls,
                                                   const float* __restrict__ ctr) {
    int n = blockIdx.x, t = threadIdx.x;
    __shared__ int fb_s;
    if (t == 0) {
        u32 cum = 0; int fstar = -1;
        for (int f = FINE - 1; f >= 1; f--) {
            cum += g_fine[n*FINE + f];
            if (cum >= (u32)KK) { fstar = f; break; }
        }
        int fb = (fstar < 0) || (g_scnt[n] > CAP_SPEC) || g_fbforce[n];
        fb_s = fb;
        g_fb[n] = fb;
        if (!fb) g_tbits[n] = ((u32)(FINE_BASE + fstar)) << 17;
    }
    __syncthreads();
    if (!fb_s) return;
    // parachute: exact full-range histogram (slow; correctness only)
    __shared__ u32 h[8192];
    for (int i = t; i < 8192; i += 1024) h[i] = 0;
    __syncthreads();
    const float* c0 = cls + (size_t)n*PER_IMG;
    const float* ctrn = ctr + n*HWp;
    for (int e = t; e < PER_IMG; e += 1024) {
        int c = e / HWp; int pix = e - c*HWp;
        float p = sigmoidf_(c0[e]);
        if (p > 0.05f) {
            float cv = sigmoidf_(ctrn[pix]);
            u32 sb = __float_as_uint(p*cv);
            atomicAdd(&h[sb >> 17], 1u);
        }
    }
    __syncthreads();
    if (t == 0) {
        u32 cum = 0; u32 tb = 0;
        for (int b = 8191; b >= 0; b--) {
            cum += h[b];
            if (cum >= (u32)KK) { tb = ((u32)b) << 17; break; }
        }
        g_tbits[n] = tb;
    }
}

// ---------------- fused filter + bitonic sort + box decode + max_c ----------------
__global__ void __launch_bounds__(1024) k_sortdecode(const float* __restrict__ cls,
                                                     const float* __restrict__ ctr,
                                                     const float* __restrict__ reg,
                                                     const float* __restrict__ pts,
                                                     const float* __restrict__ imsz) {
    __shared__ u64 sk[CAP];
    __shared__ float red[1024];
    __shared__ int cnt_s;
    int n = blockIdx.x, tid = threadIdx.x;
    if (tid == 0) cnt_s = 0;
    for (int i = tid; i < CAP; i += 1024) sk[i] = ~0ULL;
    __syncthreads();
    u32 tb = g_tbits[n];
    if (!g_fb[n]) {
        int m = g_scnt[n];
        for (int i = tid; i < m; i += 1024) {
            u64 key = g_spec[n*CAP_SPEC + i];
            u32 sb = ~((u32)(key >> 32));
            if (sb >= tb) {
                int pos = atomicAdd(&cnt_s, 1);
                if (pos < CAP) sk[pos] = key;
            }
        }
    } else {
        // parachute: full in-block recompute
        const float* c0 = cls + (size_t)n*PER_IMG;
        const float* ctrn = ctr + n*HWp;
        for (int e = tid; e < PER_IMG; e += 1024) {
            int c = e / HWp; int pix = e - c*HWp;
            float p = sigmoidf_(c0[e]);
            if (p > 0.05f) {
                float cv = sigmoidf_(ctrn[pix]);
                float s = p*cv;
                u32 sb = __float_as_uint(s);
                if (sb >= tb) {
                    int pos = atomicAdd(&cnt_s, 1);
                    if (pos < CAP) sk[pos] = (((u64)(~sb)) << 32) | (u64)((u32)pix*80u + (u32)c);
                }
            }
        }
    }
    __syncthreads();
    int cnt = cnt_s; if (cnt > CAP) cnt = CAP;
    int S = (cnt <= 2048) ? 2048 : 4096;
    for (int k2 = 2; k2 <= S; k2 <<= 1) {
        for (int j = k2 >> 1; j > 0; j >>= 1) {
            for (int i = tid; i < S; i += 1024) {
                int p = i ^ j;
                if (p > i) {
                    u64 a = sk[i], b = sk[p];
                    bool up = ((i & k2) == 0);
                    if ((a > b) == up) { sk[i] = b; sk[p] = a; }
                }
            }
            __syncthreads();
        }
    }
    float w1 = imsz[n*2] - 1.0f;
    float h1 = imsz[n*2 + 1] - 1.0f;
    const float* rg = reg + (size_t)n*4*HWp;
    float mx = 0.0f;
    {
        int r = tid;                       // KP == blockDim == 1024
        u64 key = sk[r];
        float val; int valid; u32 idx;
        if (key == ~0ULL || r >= KK) { val = -1.0f; valid = 0; idx = 0; }
        else {
            u32 sb = ~((u32)(key >> 32));
            val = __uint_as_float(sb);
            idx = (u32)key;
            valid = (val >= 0.0f) ? 1 : 0;
        }
        u32 c = idx % 80u;
        u32 loc = idx / 80u;
        float px = pts[loc*2], py = pts[loc*2 + 1];
        float d0 = rg[loc], d1 = rg[HWp + loc], d2 = rg[2*HWp + loc], d3 = rg[3*HWp + loc];
        float x1 = fminf(fmaxf(px - d0, 0.0f), w1);
        float y1 = fminf(fmaxf(py - d1, 0.0f), h1);
        float x2 = fminf(fmaxf(px + d2, 0.0f), w1);
        float y2 = fminf(fmaxf(py + d3, 0.0f), h1);
        int o = (n*KP + r)*4;
        g_boxes[o] = x1; g_boxes[o+1] = y1; g_boxes[o+2] = x2; g_boxes[o+3] = y2;
        g_label[n*KP + r] = (int)c + 1;
        g_validf[n*KP + r] = valid;
        g_score[n*KP + r] = valid ? sqrtf(fmaxf(val, 0.0f)) : -1.0f;
        mx = valid ? fmaxf(fmaxf(x1, x2), fmaxf(y1, y2)) : 0.0f;
    }
    red[tid] = mx;
    __syncthreads();
    for (int s = 512; s > 0; s >>= 1) {
        if (tid < s) red[tid] = fmaxf(red[tid], red[tid + s]);
        __syncthreads();
    }
    if (tid == 0) g_maxo[n] = red[0] + 1.0f;
}

// ---------------- 64x64 IoU tiles -> suppression bitmask (j>i only) ----------------
__global__ void k_mask() {
    int n = blockIdx.z, ti = blockIdx.y, tj = blockIdx.x;
    if (tj < ti) return;
    int t = threadIdx.x;
    float maxo = g_maxo[n];
    int i = ti*64 + t;
    int oi = (n*KP + i)*4;
    float offi = (float)g_label[n*KP + i] * maxo;
    float ax1 = g_boxes[oi]   + offi;
    float ay1 = g_boxes[oi+1] + offi;
    float ax2 = g_boxes[oi+2] + offi;
    float ay2 = g_boxes[oi+3] + offi;
    float areai = (ax2 - ax1)*(ay2 - ay1);
    __shared__ float sb[64][5];
    int j0 = tj*64 + t;
    int oj = (n*KP + j0)*4;
    float offj = (float)g_label[n*KP + j0] * maxo;
    sb[t][0] = g_boxes[oj]   + offj;
    sb[t][1] = g_boxes[oj+1] + offj;
    sb[t][2] = g_boxes[oj+2] + offj;
    sb[t][3] = g_boxes[oj+3] + offj;
    sb[t][4] = (sb[t][2] - sb[t][0])*(sb[t][3] - sb[t][1]);
    __syncthreads();
    u64 bits = 0;
    if (i < KK) {
        int jbase = tj*64;
        #pragma unroll 4
        for (int jj = 0; jj < 64; jj++) {
            int j = jbase + jj;
            if (j <= i || j >= KK) continue;
            float xx1 = fmaxf(ax1, sb[jj][0]);
            float yy1 = fmaxf(ay1, sb[jj][1]);
            float xx2 = fminf(ax2, sb[jj][2]);
            float yy2 = fminf(ay2, sb[jj][3]);
            float inter = fmaxf(xx2 - xx1, 0.0f)*fmaxf(yy2 - yy1, 0.0f);
            float den = fmaxf(areai + sb[jj][4] - inter, 1e-6f);
            if (inter / den > 0.6f) bits |= 1ull << jj;
        }
    }
    g_mask[(size_t)(n*KP + i)*16 + tj] = bits;
}

// ---------------- fused NMS scan + top-100 output + counter cleanup ----------------
__global__ void __launch_bounds__(128, 1) k_scanout(float* __restrict__ out, int out_size) {
    int n = blockIdx.x, t = threadIdx.x;
    __shared__ u64 rem[16];
    __shared__ u64 diag[64];
    __shared__ u64 keepw[16];
    if (t < 16) {
        u64 b = 0;
        for (int k = 0; k < 64; k++)
            if (!g_validf[n*KP + t*64 + k]) b |= 1ull << k;
        rem[t] = b;
    }
    __syncthreads();
    for (int c = 0; c < 16; c++) {
        if (t < 64) diag[t] = g_mask[(size_t)(n*KP + c*64 + t)*16 + c];
        __syncthreads();
        if (t == 0) {
            u64 mm[64];
            #pragma unroll
            for (int b = 0; b < 64; b++) mm[b] = diag[b];
            u64 rcur = rem[c], kb = 0;
            #pragma unroll
            for (int b = 0; b < 64; b++) {
                u64 alive = ((rcur >> b) & 1ull) ^ 1ull;
                kb |= alive << b;
                rcur |= alive ? mm[b] : 0ull;
            }
            rem[c] = rcur;
            keepw[c] = kb;
        }
        __syncthreads();
        u64 kb = keepw[c];
        for (int q = t; q < 1024; q += 128) {
            int b = q & 63, w = q >> 6;
            if (w > c && ((kb >> b) & 1ull)) {
                u64 v = g_mask[(size_t)(n*KP + c*64 + b)*16 + w];
                if (v) atomicOr(&rem[w], v);
            }
        }
        __syncthreads();
    }
    __shared__ int offs[16], noffs[16];
    __shared__ int cnts[16], ncnts[16];
    __shared__ int list[POST];
    __shared__ int mks;
    if (t < 16) {
        u64 vmask = (t == 15) ? ((1ull << 40) - 1ull) : ~0ull;
        cnts[t]  = __popcll(keepw[t]);
        ncnts[t] = __popcll(~keepw[t] & vmask);
    }
    __syncthreads();
    if (t == 0) {
        int acc = 0;
        for (int w = 0; w < 16; w++) { offs[w] = acc; acc += cnts[w]; }
        mks = acc > POST ? POST : acc;
        int acc2 = 0;
        for (int w = 0; w < 16; w++) { noffs[w] = acc2; acc2 += ncnts[w]; }
    }
    __syncthreads();
    if (t < 16) {
        u64 w = keepw[t];
        int off = offs[t];
        while (w && off < POST) { int b = __ffsll(w) - 1; list[off++] = t*64 + b; w &= w - 1; }
        u64 vmask = (t == 15) ? ((1ull << 40) - 1ull) : ~0ull;
        u64 nw = ~keepw[t] & vmask;
        int noff = mks + noffs[t];
        while (nw && noff < POST) { int b = __ffsll(nw) - 1; list[noff++] = t*64 + b; nw &= nw - 1; }
    }
    __syncthreads();
    if (t < POST) {
        int j = list[t];
        bool ov = t < mks;
        int ob = (n*KP + j)*4;
        int base = n*POST*5 + t*5;
        if (base + 4 < out_size) {
            out[base]     = g_boxes[ob];
            out[base + 1] = g_boxes[ob + 1];
            out[base + 2] = g_boxes[ob + 2];
            out[base + 3] = g_boxes[ob + 3];
            out[base + 4] = ov ? g_score[n*KP + j] : 0.0f;
        }
        int lb = Nn*POST*5 + n*POST + t;
        if (lb < out_size) out[lb] = ov ? (float)g_label[n*KP + j] : 0.0f;
        int vb = Nn*POST*5 + Nn*POST + n*POST + t;
        if (vb < out_size) out[vb] = ov ? 1.0f : 0.0f;
    }
    // cleanup for next graph replay (deterministic: zero before, zero after)
    if (t < FINE) g_fine[n*FINE + t] = 0u;
    if (t == 64) { g_scnt[n] = 0; g_fbforce[n] = 0; }
}

extern "C" void kernel_launch(void* const* d_in, const int* in_sizes, int n_in,
                              void* d_out, int out_size) {
    const float* cls  = (const float*)d_in[0];
    const float* reg  = (const float*)d_in[1];
    const float* ctr  = (const float*)d_in[2];
    const float* pts  = (const float*)d_in[3];
    const float* imsz = (const float*)d_in[4];

    k_hist<<<dim3(250, 8), 256>>>(cls, ctr);
    k_fbthresh<<<8, 1024>>>(cls, ctr);
    k_sortdecode<<<8, 1024>>>(cls, ctr, reg, pts, imsz);
    k_mask<<<dim3(16, 16, 8), 64>>>();
    k_scanout<<<8, 128>>>((float*)d_out, out_size);
}